// round 1
// baseline (speedup 1.0000x reference)
#include <cuda_runtime.h>

#define D_MODEL 2048
#define NE 64
#define TM 128
#define BK 32
#define THREADS 256

// Dynamic smem layout:
//   phase 1 (GEMM):  xs[128][33]  (floats 0 .. 4223)
//                    ws[64][33]   (floats 4224 .. 6335)
//   phase 2 (epi):   ls[128][65]  (floats 0 .. 8319)  -- aliases phase-1 region
#define XS_STRIDE 33
#define WS_STRIDE 33
#define LS_STRIDE 65
#define WS_OFF (TM * XS_STRIDE)
#define SMEM_FLOATS 8448

__global__ __launch_bounds__(THREADS, 2)
void router_kernel(const float* __restrict__ x,
                   const float* __restrict__ W,
                   const float* __restrict__ b,
                   float* __restrict__ out,
                   int n_tokens)
{
    extern __shared__ float buf[];
    float* xs = buf;            // [TM][XS_STRIDE]
    float* ws = buf + WS_OFF;   // [NE][WS_STRIDE]
    float* ls = buf;            // [TM][LS_STRIDE] (after final barrier of GEMM)

    const int tid = threadIdx.x;
    const int tok_base = blockIdx.x * TM;

    // micro-tile mapping: 8 expert-columns x 32 token-rows of threads
    const int ec = tid % 8;        // expert lane: experts ec, ec+8, ..., ec+56
    const int tr = tid / 8;        // token row group 0..31
    const int t0 = tr * 4;         // 4 consecutive tokens per thread

    float acc[4][8];
#pragma unroll
    for (int r = 0; r < 4; r++)
#pragma unroll
        for (int c = 0; c < 8; c++) acc[r][c] = 0.f;

    // loader mapping for x tile: 8 lanes cover 32 contiguous floats of one token row
    const int lx_tok = tid / 8;    // 0..31
    const int lx_kv  = tid % 8;    // float4 index 0..7

    for (int kc = 0; kc < D_MODEL; kc += BK) {
        // ---- load x tile: 128 tokens x BK ----
#pragma unroll
        for (int r = 0; r < 4; r++) {
            int tok = lx_tok + r * 32;
            float4 v = *reinterpret_cast<const float4*>(
                &x[(size_t)(tok_base + tok) * D_MODEL + kc + lx_kv * 4]);
            float* dst = &xs[tok * XS_STRIDE + lx_kv * 4];
            dst[0] = v.x; dst[1] = v.y; dst[2] = v.z; dst[3] = v.w;
        }
        // ---- load W tile: 64 experts x BK ----
#pragma unroll
        for (int r = 0; r < 2; r++) {
            int idx = tid + r * 256;           // 0..511
            int e  = idx >> 3;
            int kv = idx & 7;
            float4 v = *reinterpret_cast<const float4*>(
                &W[(size_t)e * D_MODEL + kc + kv * 4]);
            float* dst = &ws[e * WS_STRIDE + kv * 4];
            dst[0] = v.x; dst[1] = v.y; dst[2] = v.z; dst[3] = v.w;
        }
        __syncthreads();

#pragma unroll
        for (int k = 0; k < BK; k++) {
            float xv[4];
#pragma unroll
            for (int r = 0; r < 4; r++) xv[r] = xs[(t0 + r) * XS_STRIDE + k];
            float wv[8];
#pragma unroll
            for (int c = 0; c < 8; c++) wv[c] = ws[(ec + 8 * c) * WS_STRIDE + k];
#pragma unroll
            for (int r = 0; r < 4; r++)
#pragma unroll
                for (int c = 0; c < 8; c++)
                    acc[r][c] = fmaf(xv[r], wv[c], acc[r][c]);
        }
        __syncthreads();
    }

    // ---- write logits (+bias) into smem (aliases GEMM tiles; barrier above protects) ----
#pragma unroll
    for (int c = 0; c < 8; c++) {
        int e = ec + 8 * c;
        float be = b[e];
#pragma unroll
        for (int r = 0; r < 4; r++)
            ls[(t0 + r) * LS_STRIDE + e] = acc[r][c] + be;
    }
    __syncthreads();

    // ---- softmax + top-2 per token: one thread per token ----
    if (tid < TM) {
        const float* row = &ls[tid * LS_STRIDE];
        float m1 = -1e30f, m2 = -1e30f;
        int i1 = 0, i2 = 0;
#pragma unroll 8
        for (int e = 0; e < NE; e++) {
            float v = row[e];
            if (v > m1) { m2 = m1; i2 = i1; m1 = v; i1 = e; }
            else if (v > m2) { m2 = v; i2 = e; }
        }
        float s = 0.f;
#pragma unroll 8
        for (int e = 0; e < NE; e++)
            s += __expf(row[e] - m1);
        float inv = 1.0f / s;
        float w1 = inv;                    // exp(m1-m1)/s
        float w2 = __expf(m2 - m1) * inv;

        int g = tok_base + tid;
        int off_w = 2 * n_tokens;          // top_w block starts after top_idx block
        out[2 * g + 0] = (float)i1;
        out[2 * g + 1] = (float)i2;
        out[off_w + 2 * g + 0] = w1;
        out[off_w + 2 * g + 1] = w2;
    }
}

extern "C" void kernel_launch(void* const* d_in, const int* in_sizes, int n_in,
                              void* d_out, int out_size)
{
    const float* x = (const float*)d_in[0];
    const float* W = (const float*)d_in[1];
    const float* b = (const float*)d_in[2];
    float* out = (float*)d_out;

    int n_tokens = in_sizes[0] / D_MODEL;      // 4*8192 = 32768
    dim3 grid(n_tokens / TM);                  // 256 CTAs
    size_t smem = SMEM_FLOATS * sizeof(float); // 33792 B
    router_kernel<<<grid, THREADS, smem>>>(x, W, b, out, n_tokens);
}

// round 5
// speedup vs baseline: 2.2810x; 2.2810x over previous
#include <cuda_runtime.h>
#include <cuda_bf16.h>
#include <cstdint>
#include <cstring>

#define D_MODEL 2048
#define NE      64
#define TM      128
#define BK      32
#define NCHUNK  (D_MODEL / BK)   // 64
#define THREADS 256
#define SROW    28               // b32 stride per row: (28g+tg)%32 is a permutation; 112B rows, 16B aligned

// smem float offsets
#define BIAS 0
#define XH   64
#define XM   (XH + TM * SROW)    // 3648
#define XL   (XM + TM * SROW)    // 7232
#define WH   (XL + TM * SROW)    // 10816
#define WM   (WH + NE * SROW)    // 12608
#define WL   (WM + NE * SROW)    // 14400
#define SMEM_FLOATS (WL + NE * SROW)   // 16192
#define SMEM_BYTES  (SMEM_FLOATS * 4)  // 64768
// epilogue logits alias the tile region
#define LS        64
#define LS_STRIDE 65

__device__ __forceinline__ uint32_t bf16pair(float lo, float hi) {
    __nv_bfloat162 p = __floats2bfloat162_rn(lo, hi);
    uint32_t u; memcpy(&u, &p, 4); return u;
}

// exact 3-way bf16 split of a pair of fp32 (v = h + m + l up to 2^-26)
__device__ __forceinline__ void split_pair(float v0, float v1,
                                           uint32_t& H, uint32_t& M, uint32_t& L) {
    H = bf16pair(v0, v1);
    float h0 = __uint_as_float(H << 16);
    float h1 = __uint_as_float(H & 0xffff0000u);
    float r0 = v0 - h0, r1 = v1 - h1;          // exact
    M = bf16pair(r0, r1);
    float m0 = __uint_as_float(M << 16);
    float m1 = __uint_as_float(M & 0xffff0000u);
    L = bf16pair(r0 - m0, r1 - m1);
}

__device__ __forceinline__ void mma_bf16(float* d, const uint32_t* a, const uint32_t* b) {
    asm volatile(
        "mma.sync.aligned.m16n8k16.row.col.f32.bf16.bf16.f32 "
        "{%0,%1,%2,%3}, {%4,%5,%6,%7}, {%8,%9}, {%0,%1,%2,%3};"
        : "+f"(d[0]), "+f"(d[1]), "+f"(d[2]), "+f"(d[3])
        : "r"(a[0]), "r"(a[1]), "r"(a[2]), "r"(a[3]), "r"(b[0]), "r"(b[1]));
}

__global__ __launch_bounds__(THREADS, 1)
void router_bf16x3_kernel(const float* __restrict__ x,
                          const float* __restrict__ W,
                          const float* __restrict__ b,
                          float* __restrict__ out,
                          int n_tokens)
{
    extern __shared__ float s[];
    const int tid  = threadIdx.x;
    const int lane = tid & 31;
    const int wid  = tid >> 5;
    const int g    = lane >> 2;      // groupID 0..7
    const int tg   = lane & 3;       // thread-in-group 0..3
    const int m_base = (wid & 3) * 32;
    const int n_base = (wid >> 2) * 32;
    const int tok_base = blockIdx.x * TM;

    if (tid < NE) s[BIAS + tid] = b[tid];

    float accM[2][4][4], accS[2][4][4];
#pragma unroll
    for (int mi = 0; mi < 2; mi++)
#pragma unroll
        for (int ni = 0; ni < 4; ni++)
#pragma unroll
            for (int j = 0; j < 4; j++) { accM[mi][ni][j] = 0.f; accS[mi][ni][j] = 0.f; }

    // loaders: groups of 8 fp32. x: 128*32/8 = 512 groups (2/thread); W: 256 groups (1/thread)
    int xrow[2], xkg[2];
#pragma unroll
    for (int it = 0; it < 2; it++) { int gg = tid + it * 256; xrow[it] = gg >> 2; xkg[it] = gg & 3; }
    const int wrow = tid >> 2, wkg = tid & 3;

    float4 xr[2][2], wr[2];
#pragma unroll
    for (int it = 0; it < 2; it++) {
        const float4* src = reinterpret_cast<const float4*>(
            x + (size_t)(tok_base + xrow[it]) * D_MODEL + xkg[it] * 8);
        xr[it][0] = src[0]; xr[it][1] = src[1];
    }
    {
        const float4* src = reinterpret_cast<const float4*>(
            W + (size_t)wrow * D_MODEL + wkg * 8);
        wr[0] = src[0]; wr[1] = src[1];
    }

#pragma unroll 1
    for (int c = 0; c < NCHUNK; c++) {
        // ---- convert staged regs -> smem (h/m/l bf16 pair components) ----
#pragma unroll
        for (int it = 0; it < 2; it++) {
            float v[8] = {xr[it][0].x, xr[it][0].y, xr[it][0].z, xr[it][0].w,
                          xr[it][1].x, xr[it][1].y, xr[it][1].z, xr[it][1].w};
            uint32_t H[4], M[4], L[4];
#pragma unroll
            for (int j = 0; j < 4; j++) split_pair(v[2*j], v[2*j+1], H[j], M[j], L[j]);
            int o = xrow[it] * SROW + xkg[it] * 4;
            *reinterpret_cast<uint4*>(&s[XH + o]) = make_uint4(H[0], H[1], H[2], H[3]);
            *reinterpret_cast<uint4*>(&s[XM + o]) = make_uint4(M[0], M[1], M[2], M[3]);
            *reinterpret_cast<uint4*>(&s[XL + o]) = make_uint4(L[0], L[1], L[2], L[3]);
        }
        {
            float v[8] = {wr[0].x, wr[0].y, wr[0].z, wr[0].w,
                          wr[1].x, wr[1].y, wr[1].z, wr[1].w};
            uint32_t H[4], M[4], L[4];
#pragma unroll
            for (int j = 0; j < 4; j++) split_pair(v[2*j], v[2*j+1], H[j], M[j], L[j]);
            int o = wrow * SROW + wkg * 4;
            *reinterpret_cast<uint4*>(&s[WH + o]) = make_uint4(H[0], H[1], H[2], H[3]);
            *reinterpret_cast<uint4*>(&s[WM + o]) = make_uint4(M[0], M[1], M[2], M[3]);
            *reinterpret_cast<uint4*>(&s[WL + o]) = make_uint4(L[0], L[1], L[2], L[3]);
        }
        __syncthreads();

        // ---- prefetch next chunk (overlaps with mma below) ----
        if (c + 1 < NCHUNK) {
            const int kc = (c + 1) * BK;
#pragma unroll
            for (int it = 0; it < 2; it++) {
                const float4* src = reinterpret_cast<const float4*>(
                    x + (size_t)(tok_base + xrow[it]) * D_MODEL + kc + xkg[it] * 8);
                xr[it][0] = src[0]; xr[it][1] = src[1];
            }
            const float4* src = reinterpret_cast<const float4*>(
                W + (size_t)wrow * D_MODEL + kc + wkg * 8);
            wr[0] = src[0]; wr[1] = src[1];
        }

        // ---- compute: 2 k16-steps, 6 component products, magnitude-binned accs ----
#pragma unroll
        for (int kk = 0; kk < 2; kk++) {
            const int kb = kk * 8;
            uint32_t aH[2][4], aM[2][4], aL[2][4];
#pragma unroll
            for (int mi = 0; mi < 2; mi++) {
                int r = m_base + mi * 16 + g;
                int o0 = r * SROW + kb + tg;
                int o1 = (r + 8) * SROW + kb + tg;
                aH[mi][0] = __float_as_uint(s[XH + o0]);
                aH[mi][1] = __float_as_uint(s[XH + o1]);
                aH[mi][2] = __float_as_uint(s[XH + o0 + 4]);
                aH[mi][3] = __float_as_uint(s[XH + o1 + 4]);
                aM[mi][0] = __float_as_uint(s[XM + o0]);
                aM[mi][1] = __float_as_uint(s[XM + o1]);
                aM[mi][2] = __float_as_uint(s[XM + o0 + 4]);
                aM[mi][3] = __float_as_uint(s[XM + o1 + 4]);
                aL[mi][0] = __float_as_uint(s[XL + o0]);
                aL[mi][1] = __float_as_uint(s[XL + o1]);
                aL[mi][2] = __float_as_uint(s[XL + o0 + 4]);
                aL[mi][3] = __float_as_uint(s[XL + o1 + 4]);
            }
            uint32_t bH[4][2], bM[4][2], bL[4][2];
#pragma unroll
            for (int ni = 0; ni < 4; ni++) {
                int n = n_base + ni * 8 + g;
                int o = n * SROW + kb + tg;
                bH[ni][0] = __float_as_uint(s[WH + o]);
                bH[ni][1] = __float_as_uint(s[WH + o + 4]);
                bM[ni][0] = __float_as_uint(s[WM + o]);
                bM[ni][1] = __float_as_uint(s[WM + o + 4]);
                bL[ni][0] = __float_as_uint(s[WL + o]);
                bL[ni][1] = __float_as_uint(s[WL + o + 4]);
            }
            // product 1: h*H -> acc_main (8 independent chains)
#pragma unroll
            for (int mi = 0; mi < 2; mi++)
#pragma unroll
                for (int ni = 0; ni < 4; ni++)
                    mma_bf16(accM[mi][ni], aH[mi], bH[ni]);
            // products 2-6: cross/small terms -> acc_small
#pragma unroll
            for (int mi = 0; mi < 2; mi++)
#pragma unroll
                for (int ni = 0; ni < 4; ni++)
                    mma_bf16(accS[mi][ni], aH[mi], bM[ni]);
#pragma unroll
            for (int mi = 0; mi < 2; mi++)
#pragma unroll
                for (int ni = 0; ni < 4; ni++)
                    mma_bf16(accS[mi][ni], aM[mi], bH[ni]);
#pragma unroll
            for (int mi = 0; mi < 2; mi++)
#pragma unroll
                for (int ni = 0; ni < 4; ni++)
                    mma_bf16(accS[mi][ni], aM[mi], bM[ni]);
#pragma unroll
            for (int mi = 0; mi < 2; mi++)
#pragma unroll
                for (int ni = 0; ni < 4; ni++)
                    mma_bf16(accS[mi][ni], aH[mi], bL[ni]);
#pragma unroll
            for (int mi = 0; mi < 2; mi++)
#pragma unroll
                for (int ni = 0; ni < 4; ni++)
                    mma_bf16(accS[mi][ni], aL[mi], bH[ni]);
        }
        __syncthreads();
    }

    // ---- combine accs (IEEE), dump logits to smem ----
#pragma unroll
    for (int mi = 0; mi < 2; mi++)
#pragma unroll
        for (int ni = 0; ni < 4; ni++) {
            int r0 = m_base + mi * 16 + g;
            int c0 = n_base + ni * 8 + 2 * tg;
            s[LS + r0 * LS_STRIDE + c0]           = accM[mi][ni][0] + accS[mi][ni][0];
            s[LS + r0 * LS_STRIDE + c0 + 1]       = accM[mi][ni][1] + accS[mi][ni][1];
            s[LS + (r0 + 8) * LS_STRIDE + c0]     = accM[mi][ni][2] + accS[mi][ni][2];
            s[LS + (r0 + 8) * LS_STRIDE + c0 + 1] = accM[mi][ni][3] + accS[mi][ni][3];
        }
    __syncthreads();

    // ---- softmax + top-2 (proven R1 epilogue) ----
    if (tid < TM) {
        const float* row = &s[LS + tid * LS_STRIDE];
        const float* bs  = &s[BIAS];
        float logit[64];
#pragma unroll
        for (int e = 0; e < 64; e++) logit[e] = row[e] + bs[e];

        float m1 = -1e30f, m2 = -1e30f;
        int i1 = 0, i2 = 0;
#pragma unroll
        for (int e = 0; e < 64; e++) {
            float v = logit[e];
            if (v > m1)      { m2 = m1; i2 = i1; m1 = v; i1 = e; }
            else if (v > m2) { m2 = v; i2 = e; }
        }
        float ssum = 0.f;
#pragma unroll
        for (int e = 0; e < 64; e++) ssum += __expf(logit[e] - m1);
        float inv = 1.0f / ssum;

        int gt = tok_base + tid;
        int ow = 2 * n_tokens;
        out[2 * gt + 0] = (float)i1;
        out[2 * gt + 1] = (float)i2;
        out[ow + 2 * gt + 0] = inv;
        out[ow + 2 * gt + 1] = __expf(m2 - m1) * inv;
    }
}

extern "C" void kernel_launch(void* const* d_in, const int* in_sizes, int n_in,
                              void* d_out, int out_size)
{
    const float* x = (const float*)d_in[0];
    const float* W = (const float*)d_in[1];
    const float* b = (const float*)d_in[2];
    float* out = (float*)d_out;

    int n_tokens = in_sizes[0] / D_MODEL;   // 32768
    cudaFuncSetAttribute(router_bf16x3_kernel,
                         cudaFuncAttributeMaxDynamicSharedMemorySize, SMEM_BYTES);
    dim3 grid(n_tokens / TM);               // 256 CTAs
    router_bf16x3_kernel<<<grid, THREADS, SMEM_BYTES>>>(x, W, b, out, n_tokens);
}

// round 7
// speedup vs baseline: 2.3925x; 1.0488x over previous
#include <cuda_runtime.h>
#include <cuda_bf16.h>
#include <cstdint>
#include <cstring>

#define D_MODEL 2048
#define NE      64
#define TM      128
#define BK      32
#define NCHUNK  (D_MODEL / BK)   // 64
#define THREADS 256
#define SROW    28               // b32 stride per row: conflict-free frag LDS; 112B rows

// per-buffer tile layout (floats, relative to tile base)
#define T_XH 0
#define T_XM (T_XH + TM * SROW)      // 3584
#define T_XL (T_XM + TM * SROW)      // 7168
#define T_WH (T_XL + TM * SROW)      // 10752
#define T_WM (T_WH + NE * SROW)      // 12544
#define T_WL (T_WM + NE * SROW)      // 14336
#define TILE_FLOATS (T_WL + NE * SROW)   // 16128

#define BIAS  0
#define TILE0 64
#define SMEM_FLOATS (TILE0 + 2 * TILE_FLOATS)   // 32320
#define SMEM_BYTES  (SMEM_FLOATS * 4)           // 129280

// epilogue logits alias buffer0
#define LS        TILE0
#define LS_STRIDE 65

__device__ __forceinline__ uint32_t bf16pair(float lo, float hi) {
    __nv_bfloat162 p = __floats2bfloat162_rn(lo, hi);
    uint32_t u; memcpy(&u, &p, 4); return u;
}

// exact 3-way bf16 split of a pair of fp32
__device__ __forceinline__ void split_pair(float v0, float v1,
                                           uint32_t& H, uint32_t& M, uint32_t& L) {
    H = bf16pair(v0, v1);
    float h0 = __uint_as_float(H << 16);
    float h1 = __uint_as_float(H & 0xffff0000u);
    float r0 = v0 - h0, r1 = v1 - h1;          // exact
    M = bf16pair(r0, r1);
    float m0 = __uint_as_float(M << 16);
    float m1 = __uint_as_float(M & 0xffff0000u);
    L = bf16pair(r0 - m0, r1 - m1);
}

__device__ __forceinline__ void mma_bf16(float* d, const uint32_t* a, const uint32_t* b) {
    asm volatile(
        "mma.sync.aligned.m16n8k16.row.col.f32.bf16.bf16.f32 "
        "{%0,%1,%2,%3}, {%4,%5,%6,%7}, {%8,%9}, {%0,%1,%2,%3};"
        : "+f"(d[0]), "+f"(d[1]), "+f"(d[2]), "+f"(d[3])
        : "r"(a[0]), "r"(a[1]), "r"(a[2]), "r"(a[3]), "r"(b[0]), "r"(b[1]));
}

__global__ __launch_bounds__(THREADS, 1)
void router_bf16x3_db_kernel(const float* __restrict__ x,
                             const float* __restrict__ W,
                             const float* __restrict__ b,
                             float* __restrict__ out,
                             int n_tokens)
{
    extern __shared__ float s[];
    const int tid  = threadIdx.x;
    const int lane = tid & 31;
    const int wid  = tid >> 5;
    const int g    = lane >> 2;
    const int tg   = lane & 3;
    const int m_base = (wid & 3) * 32;
    const int n_base = (wid >> 2) * 32;
    const int tok_base = blockIdx.x * TM;

    if (tid < NE) s[BIAS + tid] = b[tid];

    float accM[2][4][4], accS[2][4][4];
#pragma unroll
    for (int mi = 0; mi < 2; mi++)
#pragma unroll
        for (int ni = 0; ni < 4; ni++)
#pragma unroll
            for (int j = 0; j < 4; j++) { accM[mi][ni][j] = 0.f; accS[mi][ni][j] = 0.f; }

    // loader mapping: groups of 8 fp32. x: 512 groups (2/thread); W: 256 groups (1/thread)
    int xrow[2], xkg[2];
#pragma unroll
    for (int it = 0; it < 2; it++) { int gg = tid + it * 256; xrow[it] = gg >> 2; xkg[it] = gg & 3; }
    const int wrow = tid >> 2, wkg = tid & 3;

    const float* xp0 = x + (size_t)(tok_base + xrow[0]) * D_MODEL + xkg[0] * 8;
    const float* xp1 = x + (size_t)(tok_base + xrow[1]) * D_MODEL + xkg[1] * 8;
    const float* wp  = W + (size_t)wrow * D_MODEL + wkg * 8;
    const int xo = xrow[0] * SROW + xkg[0] * 4;   // note xrow[1]=xrow[0]+64
    const int xo1 = xrow[1] * SROW + xkg[1] * 4;
    const int wo = wrow * SROW + wkg * 4;

    float4 xr[2][2], wr[2];

    // ---- prologue: load + convert chunk 0 into buffer 0 ----
    {
        const float4* s0 = reinterpret_cast<const float4*>(xp0);
        const float4* s1 = reinterpret_cast<const float4*>(xp1);
        const float4* sw = reinterpret_cast<const float4*>(wp);
        xr[0][0] = s0[0]; xr[0][1] = s0[1];
        xr[1][0] = s1[0]; xr[1][1] = s1[1];
        wr[0] = sw[0];    wr[1] = sw[1];

        float* buf = s + TILE0;
#pragma unroll
        for (int it = 0; it < 2; it++) {
            float v[8] = {xr[it][0].x, xr[it][0].y, xr[it][0].z, xr[it][0].w,
                          xr[it][1].x, xr[it][1].y, xr[it][1].z, xr[it][1].w};
            uint32_t H[4], M[4], L[4];
#pragma unroll
            for (int j = 0; j < 4; j++) split_pair(v[2*j], v[2*j+1], H[j], M[j], L[j]);
            int o = it ? xo1 : xo;
            *reinterpret_cast<uint4*>(&buf[T_XH + o]) = make_uint4(H[0], H[1], H[2], H[3]);
            *reinterpret_cast<uint4*>(&buf[T_XM + o]) = make_uint4(M[0], M[1], M[2], M[3]);
            *reinterpret_cast<uint4*>(&buf[T_XL + o]) = make_uint4(L[0], L[1], L[2], L[3]);
        }
        {
            float v[8] = {wr[0].x, wr[0].y, wr[0].z, wr[0].w,
                          wr[1].x, wr[1].y, wr[1].z, wr[1].w};
            uint32_t H[4], M[4], L[4];
#pragma unroll
            for (int j = 0; j < 4; j++) split_pair(v[2*j], v[2*j+1], H[j], M[j], L[j]);
            *reinterpret_cast<uint4*>(&buf[T_WH + wo]) = make_uint4(H[0], H[1], H[2], H[3]);
            *reinterpret_cast<uint4*>(&buf[T_WM + wo]) = make_uint4(M[0], M[1], M[2], M[3]);
            *reinterpret_cast<uint4*>(&buf[T_WL + wo]) = make_uint4(L[0], L[1], L[2], L[3]);
        }
    }
    __syncthreads();

#pragma unroll 1
    for (int c = 0; c < NCHUNK; c++) {
        float* bufc = s + TILE0 + (c & 1) * TILE_FLOATS;
        float* bufn = s + TILE0 + ((c & 1) ^ 1) * TILE_FLOATS;
        const bool more = (c + 1 < NCHUNK);

        // ---- prefetch chunk c+1 (LDG issues early; covered by MMA block) ----
        if (more) {
            const int kc = (c + 1) * BK;
            const float4* s0 = reinterpret_cast<const float4*>(xp0 + kc);
            const float4* s1 = reinterpret_cast<const float4*>(xp1 + kc);
            const float4* sw = reinterpret_cast<const float4*>(wp + kc);
            xr[0][0] = s0[0]; xr[0][1] = s0[1];
            xr[1][0] = s1[0]; xr[1][1] = s1[1];
            wr[0] = sw[0];    wr[1] = sw[1];
        }

        // ---- MMA on current buffer: 2 k16-steps, 6 products ----
#pragma unroll
        for (int kk = 0; kk < 2; kk++) {
            const int kb = kk * 8;
            uint32_t aH[2][4], aM[2][4], aL[2][4];
#pragma unroll
            for (int mi = 0; mi < 2; mi++) {
                int r = m_base + mi * 16 + g;
                int o0 = r * SROW + kb + tg;
                int o1 = (r + 8) * SROW + kb + tg;
                aH[mi][0] = __float_as_uint(bufc[T_XH + o0]);
                aH[mi][1] = __float_as_uint(bufc[T_XH + o1]);
                aH[mi][2] = __float_as_uint(bufc[T_XH + o0 + 4]);
                aH[mi][3] = __float_as_uint(bufc[T_XH + o1 + 4]);
                aM[mi][0] = __float_as_uint(bufc[T_XM + o0]);
                aM[mi][1] = __float_as_uint(bufc[T_XM + o1]);
                aM[mi][2] = __float_as_uint(bufc[T_XM + o0 + 4]);
                aM[mi][3] = __float_as_uint(bufc[T_XM + o1 + 4]);
                aL[mi][0] = __float_as_uint(bufc[T_XL + o0]);
                aL[mi][1] = __float_as_uint(bufc[T_XL + o1]);
                aL[mi][2] = __float_as_uint(bufc[T_XL + o0 + 4]);
                aL[mi][3] = __float_as_uint(bufc[T_XL + o1 + 4]);
            }
            uint32_t bH[4][2], bM[4][2], bL[4][2];
#pragma unroll
            for (int ni = 0; ni < 4; ni++) {
                int n = n_base + ni * 8 + g;
                int o = n * SROW + kb + tg;
                bH[ni][0] = __float_as_uint(bufc[T_WH + o]);
                bH[ni][1] = __float_as_uint(bufc[T_WH + o + 4]);
                bM[ni][0] = __float_as_uint(bufc[T_WM + o]);
                bM[ni][1] = __float_as_uint(bufc[T_WM + o + 4]);
                bL[ni][0] = __float_as_uint(bufc[T_WL + o]);
                bL[ni][1] = __float_as_uint(bufc[T_WL + o + 4]);
            }
#pragma unroll
            for (int mi = 0; mi < 2; mi++)
#pragma unroll
                for (int ni = 0; ni < 4; ni++)
                    mma_bf16(accM[mi][ni], aH[mi], bH[ni]);
#pragma unroll
            for (int mi = 0; mi < 2; mi++)
#pragma unroll
                for (int ni = 0; ni < 4; ni++)
                    mma_bf16(accS[mi][ni], aH[mi], bM[ni]);
#pragma unroll
            for (int mi = 0; mi < 2; mi++)
#pragma unroll
                for (int ni = 0; ni < 4; ni++)
                    mma_bf16(accS[mi][ni], aM[mi], bH[ni]);
#pragma unroll
            for (int mi = 0; mi < 2; mi++)
#pragma unroll
                for (int ni = 0; ni < 4; ni++)
                    mma_bf16(accS[mi][ni], aM[mi], bM[ni]);
#pragma unroll
            for (int mi = 0; mi < 2; mi++)
#pragma unroll
                for (int ni = 0; ni < 4; ni++)
                    mma_bf16(accS[mi][ni], aH[mi], bL[ni]);
#pragma unroll
            for (int mi = 0; mi < 2; mi++)
#pragma unroll
                for (int ni = 0; ni < 4; ni++)
                    mma_bf16(accS[mi][ni], aL[mi], bH[ni]);
        }

        // ---- convert chunk c+1 into next buffer (overlaps other warps' MMAs) ----
        if (more) {
#pragma unroll
            for (int it = 0; it < 2; it++) {
                float v[8] = {xr[it][0].x, xr[it][0].y, xr[it][0].z, xr[it][0].w,
                              xr[it][1].x, xr[it][1].y, xr[it][1].z, xr[it][1].w};
                uint32_t H[4], M[4], L[4];
#pragma unroll
                for (int j = 0; j < 4; j++) split_pair(v[2*j], v[2*j+1], H[j], M[j], L[j]);
                int o = it ? xo1 : xo;
                *reinterpret_cast<uint4*>(&bufn[T_XH + o]) = make_uint4(H[0], H[1], H[2], H[3]);
                *reinterpret_cast<uint4*>(&bufn[T_XM + o]) = make_uint4(M[0], M[1], M[2], M[3]);
                *reinterpret_cast<uint4*>(&bufn[T_XL + o]) = make_uint4(L[0], L[1], L[2], L[3]);
            }
            {
                float v[8] = {wr[0].x, wr[0].y, wr[0].z, wr[0].w,
                              wr[1].x, wr[1].y, wr[1].z, wr[1].w};
                uint32_t H[4], M[4], L[4];
#pragma unroll
                for (int j = 0; j < 4; j++) split_pair(v[2*j], v[2*j+1], H[j], M[j], L[j]);
                *reinterpret_cast<uint4*>(&bufn[T_WH + wo]) = make_uint4(H[0], H[1], H[2], H[3]);
                *reinterpret_cast<uint4*>(&bufn[T_WM + wo]) = make_uint4(M[0], M[1], M[2], M[3]);
                *reinterpret_cast<uint4*>(&bufn[T_WL + wo]) = make_uint4(L[0], L[1], L[2], L[3]);
            }
        }
        __syncthreads();
    }

    // ---- combine accs (IEEE), dump logits ----
#pragma unroll
    for (int mi = 0; mi < 2; mi++)
#pragma unroll
        for (int ni = 0; ni < 4; ni++) {
            int r0 = m_base + mi * 16 + g;
            int c0 = n_base + ni * 8 + 2 * tg;
            s[LS + r0 * LS_STRIDE + c0]           = accM[mi][ni][0] + accS[mi][ni][0];
            s[LS + r0 * LS_STRIDE + c0 + 1]       = accM[mi][ni][1] + accS[mi][ni][1];
            s[LS + (r0 + 8) * LS_STRIDE + c0]     = accM[mi][ni][2] + accS[mi][ni][2];
            s[LS + (r0 + 8) * LS_STRIDE + c0 + 1] = accM[mi][ni][3] + accS[mi][ni][3];
        }
    __syncthreads();

    // ---- softmax + top-2 ----
    if (tid < TM) {
        const float* row = &s[LS + tid * LS_STRIDE];
        const float* bs  = &s[BIAS];
        float logit[64];
#pragma unroll
        for (int e = 0; e < 64; e++) logit[e] = row[e] + bs[e];

        float m1 = -1e30f, m2 = -1e30f;
        int i1 = 0, i2 = 0;
#pragma unroll
        for (int e = 0; e < 64; e++) {
            float v = logit[e];
            if (v > m1)      { m2 = m1; i2 = i1; m1 = v; i1 = e; }
            else if (v > m2) { m2 = v; i2 = e; }
        }
        float ssum = 0.f;
#pragma unroll
        for (int e = 0; e < 64; e++) ssum += __expf(logit[e] - m1);
        float inv = 1.0f / ssum;

        int gt = tok_base + tid;
        int ow = 2 * n_tokens;
        out[2 * gt + 0] = (float)i1;
        out[2 * gt + 1] = (float)i2;
        out[ow + 2 * gt + 0] = inv;
        out[ow + 2 * gt + 1] = __expf(m2 - m1) * inv;
    }
}

extern "C" void kernel_launch(void* const* d_in, const int* in_sizes, int n_in,
                              void* d_out, int out_size)
{
    const float* x = (const float*)d_in[0];
    const float* W = (const float*)d_in[1];
    const float* b = (const float*)d_in[2];
    float* out = (float*)d_out;

    int n_tokens = in_sizes[0] / D_MODEL;   // 32768
    cudaFuncSetAttribute(router_bf16x3_db_kernel,
                         cudaFuncAttributeMaxDynamicSharedMemorySize, SMEM_BYTES);
    dim3 grid(n_tokens / TM);               // 256 CTAs
    router_bf16x3_db_kernel<<<grid, THREADS, SMEM_BYTES>>>(x, W, b, out, n_tokens);
}